// round 8
// baseline (speedup 1.0000x reference)
#include <cuda_runtime.h>
#include <cuda_bf16.h>
#include <cstdint>
#include <cstddef>

// ---------------------------------------------------------------------------
// Problem dims
// ---------------------------------------------------------------------------
#define BDIM   8192
#define DIN    2048
#define HDIM   2048
#define DOUT   1024
#define NCOMP  4

// ---------------------------------------------------------------------------
// Helpers (sm_103-safe)
// ---------------------------------------------------------------------------
__device__ __forceinline__ uint32_t smem_u32(const void* p) {
    uint32_t a;
    asm("{ .reg .u64 t; cvta.to.shared.u64 t, %1; cvt.u32.u64 %0, t; }"
        : "=r"(a) : "l"(p));
    return a;
}

#define SMEM_SWIZZLE_128B(o) ((o) ^ (((o) >> 3) & 0x70))

__device__ __forceinline__ void cp_async16(uint32_t dst, const void* src) {
    asm volatile("cp.async.cg.shared.global [%0], [%1], 16;"
                 :: "r"(dst), "l"(__cvta_generic_to_global(src)));
}
#define CP_COMMIT() asm volatile("cp.async.commit_group;" ::: "memory")
#define CP_WAIT(n)  asm volatile("cp.async.wait_group %0;" :: "n"(n) : "memory")

__device__ __forceinline__ void ldsm4(uint32_t* r, uint32_t addr) {
    asm volatile("ldmatrix.sync.aligned.m8n8.x4.shared.b16 {%0,%1,%2,%3}, [%4];"
                 : "=r"(r[0]), "=r"(r[1]), "=r"(r[2]), "=r"(r[3]) : "r"(addr));
}

__device__ __forceinline__ void mma16816(float* d, const uint32_t* a,
                                         uint32_t b0, uint32_t b1) {
    asm volatile(
        "mma.sync.aligned.m16n8k16.row.col.f32.bf16.bf16.f32 "
        "{%0,%1,%2,%3}, {%4,%5,%6,%7}, {%8,%9}, {%0,%1,%2,%3};"
        : "+f"(d[0]), "+f"(d[1]), "+f"(d[2]), "+f"(d[3])
        : "r"(a[0]), "r"(a[1]), "r"(a[2]), "r"(a[3]), "r"(b0), "r"(b1));
}

// ---------------------------------------------------------------------------
// Scratch buffers (__device__ globals; no cudaMalloc allowed)
// ---------------------------------------------------------------------------
__device__ __align__(16) __nv_bfloat16 g_wh0[HDIM * DIN];
__device__ __align__(16) __nv_bfloat16 g_wl0[HDIM * DIN];
__device__ __align__(16) __nv_bfloat16 g_wh1[HDIM * HDIM];
__device__ __align__(16) __nv_bfloat16 g_wl1[HDIM * HDIM];
__device__ __align__(16) __nv_bfloat16 g_wh2[DOUT * HDIM];
__device__ __align__(16) __nv_bfloat16 g_wl2[DOUT * HDIM];
__device__ __align__(16) float g_b0[HDIM];
__device__ __align__(16) float g_b1[HDIM];
__device__ __align__(16) float g_b2[DOUT];
__device__ __align__(16) __nv_bfloat16 g_a0h[BDIM * DIN];
__device__ __align__(16) __nv_bfloat16 g_a0l[BDIM * DIN];
__device__ __align__(16) __nv_bfloat16 g_a1h[BDIM * HDIM];
__device__ __align__(16) __nv_bfloat16 g_a1l[BDIM * HDIM];
__device__ __align__(16) __nv_bfloat16 g_a2h[BDIM * HDIM];
__device__ __align__(16) __nv_bfloat16 g_a2l[BDIM * HDIM];

// ---------------------------------------------------------------------------
// Prep kernels: fold mixture into effective bf16 hi/lo weights + fp32 bias
// ---------------------------------------------------------------------------
__device__ __forceinline__ void mix_coefs(const float* ml, const float* lv,
                                          float* cmu, float* cn) {
    float m[NCOMP], mx = -1e30f, s = 0.f, e[NCOMP];
    #pragma unroll
    for (int k = 0; k < NCOMP; k++) { m[k] = ml[k]; mx = fmaxf(mx, m[k]); }
    #pragma unroll
    for (int k = 0; k < NCOMP; k++) { e[k] = expf(m[k] - mx); s += e[k]; }
    #pragma unroll
    for (int k = 0; k < NCOMP; k++) {
        float w = e[k] / s;
        cmu[k] = w;
        cn[k]  = w * expf(0.5f * lv[k]);
    }
}

__global__ void prep_weights_kernel(const float* __restrict__ wmu,
                                    const float* __restrict__ wn,
                                    const float* __restrict__ wlv,
                                    const float* __restrict__ ml,
                                    __nv_bfloat16* __restrict__ whi,
                                    __nv_bfloat16* __restrict__ wlo,
                                    int n) {
    __shared__ float cmu[NCOMP], cn[NCOMP];
    if (threadIdx.x == 0) mix_coefs(ml, wlv, cmu, cn);
    __syncthreads();
    int n4 = n >> 2;
    for (int i = blockIdx.x * blockDim.x + threadIdx.x; i < n4;
         i += gridDim.x * blockDim.x) {
        float4 acc = make_float4(0.f, 0.f, 0.f, 0.f);
        #pragma unroll
        for (int k = 0; k < NCOMP; k++) {
            float4 a = ((const float4*)wmu)[(size_t)k * n4 + i];
            float4 b = ((const float4*)wn)[(size_t)k * n4 + i];
            acc.x += cmu[k] * a.x + cn[k] * b.x;
            acc.y += cmu[k] * a.y + cn[k] * b.y;
            acc.z += cmu[k] * a.z + cn[k] * b.z;
            acc.w += cmu[k] * a.w + cn[k] * b.w;
        }
        __nv_bfloat16 h0 = __float2bfloat16(acc.x);
        __nv_bfloat16 h1 = __float2bfloat16(acc.y);
        __nv_bfloat16 h2 = __float2bfloat16(acc.z);
        __nv_bfloat16 h3 = __float2bfloat16(acc.w);
        __nv_bfloat16 l0 = __float2bfloat16(acc.x - __bfloat162float(h0));
        __nv_bfloat16 l1 = __float2bfloat16(acc.y - __bfloat162float(h1));
        __nv_bfloat16 l2 = __float2bfloat16(acc.z - __bfloat162float(h2));
        __nv_bfloat16 l3 = __float2bfloat16(acc.w - __bfloat162float(h3));
        ((__nv_bfloat162*)whi)[2 * (size_t)i]     = __halves2bfloat162(h0, h1);
        ((__nv_bfloat162*)whi)[2 * (size_t)i + 1] = __halves2bfloat162(h2, h3);
        ((__nv_bfloat162*)wlo)[2 * (size_t)i]     = __halves2bfloat162(l0, l1);
        ((__nv_bfloat162*)wlo)[2 * (size_t)i + 1] = __halves2bfloat162(l2, l3);
    }
}

__global__ void prep_bias_kernel(const float* __restrict__ bmu,
                                 const float* __restrict__ bn,
                                 const float* __restrict__ blv,
                                 const float* __restrict__ ml,
                                 float* __restrict__ out, int O) {
    __shared__ float cmu[NCOMP], cn[NCOMP];
    if (threadIdx.x == 0) mix_coefs(ml, blv, cmu, cn);
    __syncthreads();
    int o = blockIdx.x * blockDim.x + threadIdx.x;
    if (o < O) {
        float e = 0.f;
        #pragma unroll
        for (int k = 0; k < NCOMP; k++)
            e += cmu[k] * bmu[k * O + o] + cn[k] * bn[k * O + o];
        out[o] = e;
    }
}

__global__ void split_x_kernel(const float* __restrict__ x,
                               __nv_bfloat16* __restrict__ xh,
                               __nv_bfloat16* __restrict__ xl, int n) {
    int n4 = n >> 2;
    for (int i = blockIdx.x * blockDim.x + threadIdx.x; i < n4;
         i += gridDim.x * blockDim.x) {
        float4 v = ((const float4*)x)[i];
        __nv_bfloat16 h0 = __float2bfloat16(v.x);
        __nv_bfloat16 h1 = __float2bfloat16(v.y);
        __nv_bfloat16 h2 = __float2bfloat16(v.z);
        __nv_bfloat16 h3 = __float2bfloat16(v.w);
        __nv_bfloat16 l0 = __float2bfloat16(v.x - __bfloat162float(h0));
        __nv_bfloat16 l1 = __float2bfloat16(v.y - __bfloat162float(h1));
        __nv_bfloat16 l2 = __float2bfloat16(v.z - __bfloat162float(h2));
        __nv_bfloat16 l3 = __float2bfloat16(v.w - __bfloat162float(h3));
        ((__nv_bfloat162*)xh)[2 * (size_t)i]     = __halves2bfloat162(h0, h1);
        ((__nv_bfloat162*)xh)[2 * (size_t)i + 1] = __halves2bfloat162(h2, h3);
        ((__nv_bfloat162*)xl)[2 * (size_t)i]     = __halves2bfloat162(l0, l1);
        ((__nv_bfloat162*)xl)[2 * (size_t)i + 1] = __halves2bfloat162(l2, l3);
    }
}

// ---------------------------------------------------------------------------
// mma.sync GEMM:  C[B,O] = A[B,I] @ W[O,I]^T + bias   (split bf16 hi/lo)
// CTA tile 128x256, BK=64, 16 warps (2x8), warp tile 64x32.
// 4 warps/SMSP for latency hiding; acc = 64 regs/thread.
// 2 cp.async stages (96 KB each), ONE __syncthreads per iter.
// ---------------------------------------------------------------------------
#define BM 128
#define BN 256
#define BK 64
#define NT 512
#define STAGE_BYTES 98304
#define OFF_AL 16384
#define OFF_WH 32768
#define OFF_WL 65536
#define GEMM_SMEM_TOTAL (2 * STAGE_BYTES)

__global__ void __launch_bounds__(NT, 1)
gemm_split_bf16(const __nv_bfloat16* __restrict__ Ah,
                const __nv_bfloat16* __restrict__ Al,
                const __nv_bfloat16* __restrict__ Wh,
                const __nv_bfloat16* __restrict__ Wl,
                const float* __restrict__ bias,
                int Idim, int Odim, int relu_split,
                __nv_bfloat16* __restrict__ Oh,
                __nv_bfloat16* __restrict__ Ol,
                float* __restrict__ Of) {
    extern __shared__ char smem[];
    const uint32_t sb = smem_u32(smem);
    const int tid = threadIdx.x;
    const int wid = tid >> 5, l = tid & 31;
    const int n0 = blockIdx.x * BN, m0 = blockIdx.y * BM;
    const int wm = (wid >> 3) * 64;    // warp m offset (2 m-bands)
    const int wn = (wid & 7) * 32;     // warp n offset (8 n-bands)
    const int lm = l >> 3, lr = l & 7; // ldmatrix lane decomposition

    float acc[4][4][4];
    #pragma unroll
    for (int i = 0; i < 4; i++)
        #pragma unroll
        for (int j = 0; j < 4; j++)
            #pragma unroll
            for (int q = 0; q < 4; q++) acc[i][j][q] = 0.f;

    const int nk = Idim / BK;

    auto issue = [&](int s, int k0) {
        uint32_t base = sb + s * STAGE_BYTES;
        #pragma unroll
        for (int j = 0; j < 2; j++) {          // A hi+lo
            int c = tid + j * NT;
            int row = c >> 3, col = c & 7;
            uint32_t so = SMEM_SWIZZLE_128B((uint32_t)(row * 128 + col * 16));
            size_t g = (size_t)(m0 + row) * Idim + k0 + col * 8;
            cp_async16(base + so, Ah + g);
            cp_async16(base + OFF_AL + so, Al + g);
        }
        #pragma unroll
        for (int j = 0; j < 4; j++) {          // W hi+lo
            int c = tid + j * NT;
            int row = c >> 3, col = c & 7;
            uint32_t so = SMEM_SWIZZLE_128B((uint32_t)(row * 128 + col * 16));
            size_t g = (size_t)(n0 + row) * Idim + k0 + col * 8;
            cp_async16(base + OFF_WH + so, Wh + g);
            cp_async16(base + OFF_WL + so, Wl + g);
        }
    };

    issue(0, 0);
    CP_COMMIT();

    for (int it = 0; it < nk; ++it) {
        CP_WAIT(0);          // only group `it` pending -> stage ready
        __syncthreads();     // + WAR protection on stage (it+1)&1
        if (it + 1 < nk) {
            issue((it + 1) & 1, (it + 1) * BK);
            CP_COMMIT();
        }

        uint32_t bA = sb + (it & 1) * STAGE_BYTES;
        #pragma unroll
        for (int kk = 0; kk < 4; kk++) {
            uint32_t ah[4][4], al[4][4];
            #pragma unroll
            for (int mf = 0; mf < 4; mf++) {
                uint32_t off = SMEM_SWIZZLE_128B(
                    (uint32_t)((wm + mf * 16 + (lm & 1) * 8 + lr) * 128 +
                               (kk * 2 + (lm >> 1)) * 16));
                ldsm4(ah[mf], bA + off);
                ldsm4(al[mf], bA + OFF_AL + off);
            }
            #pragma unroll
            for (int nf2 = 0; nf2 < 2; nf2++) {
                uint32_t off = SMEM_SWIZZLE_128B(
                    (uint32_t)((wn + nf2 * 16 + (lm >> 1) * 8 + lr) * 128 +
                               (kk * 2 + (lm & 1)) * 16));
                uint32_t bh[4], bl[4];
                ldsm4(bh, bA + OFF_WH + off);
                ldsm4(bl, bA + OFF_WL + off);
                #pragma unroll
                for (int mf = 0; mf < 4; mf++) {
                    mma16816(acc[mf][2 * nf2],     ah[mf], bh[0], bh[1]);
                    mma16816(acc[mf][2 * nf2 + 1], ah[mf], bh[2], bh[3]);
                }
                #pragma unroll
                for (int mf = 0; mf < 4; mf++) {
                    mma16816(acc[mf][2 * nf2],     ah[mf], bl[0], bl[1]);
                    mma16816(acc[mf][2 * nf2 + 1], ah[mf], bl[2], bl[3]);
                }
                #pragma unroll
                for (int mf = 0; mf < 4; mf++) {
                    mma16816(acc[mf][2 * nf2],     al[mf], bh[0], bh[1]);
                    mma16816(acc[mf][2 * nf2 + 1], al[mf], bh[2], bh[3]);
                }
            }
        }
    }

    // Epilogue: bias (+relu+split) directly from register fragments.
    const int cb = n0 + wn;
    if (relu_split) {
        #pragma unroll
        for (int mf = 0; mf < 4; mf++) {
            int r0 = m0 + wm + mf * 16 + (l >> 2);
            #pragma unroll
            for (int nf = 0; nf < 4; nf++) {
                int col = cb + nf * 8 + 2 * (l & 3);
                float2 bv = *(const float2*)(bias + col);
                float v0 = fmaxf(acc[mf][nf][0] + bv.x, 0.f);
                float v1 = fmaxf(acc[mf][nf][1] + bv.y, 0.f);
                float v2 = fmaxf(acc[mf][nf][2] + bv.x, 0.f);
                float v3 = fmaxf(acc[mf][nf][3] + bv.y, 0.f);
                __nv_bfloat16 h0 = __float2bfloat16(v0);
                __nv_bfloat16 h1 = __float2bfloat16(v1);
                __nv_bfloat16 h2 = __float2bfloat16(v2);
                __nv_bfloat16 h3 = __float2bfloat16(v3);
                __nv_bfloat16 q0 = __float2bfloat16(v0 - __bfloat162float(h0));
                __nv_bfloat16 q1 = __float2bfloat16(v1 - __bfloat162float(h1));
                __nv_bfloat16 q2 = __float2bfloat16(v2 - __bfloat162float(h2));
                __nv_bfloat16 q3 = __float2bfloat16(v3 - __bfloat162float(h3));
                *(__nv_bfloat162*)(Oh + (size_t)r0 * Odim + col) = __halves2bfloat162(h0, h1);
                *(__nv_bfloat162*)(Oh + (size_t)(r0 + 8) * Odim + col) = __halves2bfloat162(h2, h3);
                *(__nv_bfloat162*)(Ol + (size_t)r0 * Odim + col) = __halves2bfloat162(q0, q1);
                *(__nv_bfloat162*)(Ol + (size_t)(r0 + 8) * Odim + col) = __halves2bfloat162(q2, q3);
            }
        }
    } else {
        #pragma unroll
        for (int mf = 0; mf < 4; mf++) {
            int r0 = m0 + wm + mf * 16 + (l >> 2);
            #pragma unroll
            for (int nf = 0; nf < 4; nf++) {
                int col = cb + nf * 8 + 2 * (l & 3);
                float2 bv = *(const float2*)(bias + col);
                float2 o0 = make_float2(acc[mf][nf][0] + bv.x, acc[mf][nf][1] + bv.y);
                float2 o1 = make_float2(acc[mf][nf][2] + bv.x, acc[mf][nf][3] + bv.y);
                *(float2*)(Of + (size_t)r0 * Odim + col) = o0;
                *(float2*)(Of + (size_t)(r0 + 8) * Odim + col) = o1;
            }
        }
    }
}

// ---------------------------------------------------------------------------
// Row softmax (in-place), 1024 cols, 256 threads/row
// ---------------------------------------------------------------------------
__global__ void softmax_kernel(float* __restrict__ io) {
    __shared__ float red[8];
    int b = blockIdx.x;
    float* row = io + (size_t)b * DOUT;
    int t = threadIdx.x;
    float v[4];
    float m = -1e30f;
    #pragma unroll
    for (int i = 0; i < 4; i++) { v[i] = row[t + 256 * i]; m = fmaxf(m, v[i]); }
    #pragma unroll
    for (int o = 16; o; o >>= 1) m = fmaxf(m, __shfl_xor_sync(0xffffffffu, m, o));
    if ((t & 31) == 0) red[t >> 5] = m;
    __syncthreads();
    m = red[0];
    #pragma unroll
    for (int w = 1; w < 8; w++) m = fmaxf(m, red[w]);
    float s = 0.f;
    #pragma unroll
    for (int i = 0; i < 4; i++) { v[i] = expf(v[i] - m); s += v[i]; }
    #pragma unroll
    for (int o = 16; o; o >>= 1) s += __shfl_xor_sync(0xffffffffu, s, o);
    __syncthreads();
    if ((t & 31) == 0) red[t >> 5] = s;
    __syncthreads();
    s = red[0];
    #pragma unroll
    for (int w = 1; w < 8; w++) s += red[w];
    float inv = 1.0f / s;
    #pragma unroll
    for (int i = 0; i < 4; i++) row[t + 256 * i] = v[i] * inv;
}

// ---------------------------------------------------------------------------
// Launcher
// ---------------------------------------------------------------------------
extern "C" void kernel_launch(void* const* d_in, const int* in_sizes, int n_in,
                              void* d_out, int out_size) {
    (void)in_sizes; (void)n_in; (void)out_size;
    const float* x   = (const float*)d_in[0];
    const float* wmu[3] = {(const float*)d_in[1],  (const float*)d_in[8],  (const float*)d_in[15]};
    const float* bmu[3] = {(const float*)d_in[2],  (const float*)d_in[9],  (const float*)d_in[16]};
    const float* wlv[3] = {(const float*)d_in[3],  (const float*)d_in[10], (const float*)d_in[17]};
    const float* blv[3] = {(const float*)d_in[4],  (const float*)d_in[11], (const float*)d_in[18]};
    const float* ml[3]  = {(const float*)d_in[5],  (const float*)d_in[12], (const float*)d_in[19]};
    const float* wn[3]  = {(const float*)d_in[6],  (const float*)d_in[13], (const float*)d_in[20]};
    const float* bn[3]  = {(const float*)d_in[7],  (const float*)d_in[14], (const float*)d_in[21]};

    void *wh0, *wl0, *wh1, *wl1, *wh2, *wl2, *b0, *b1, *b2;
    void *a0h, *a0l, *a1h, *a1l, *a2h, *a2l;
    cudaGetSymbolAddress(&wh0, g_wh0); cudaGetSymbolAddress(&wl0, g_wl0);
    cudaGetSymbolAddress(&wh1, g_wh1); cudaGetSymbolAddress(&wl1, g_wl1);
    cudaGetSymbolAddress(&wh2, g_wh2); cudaGetSymbolAddress(&wl2, g_wl2);
    cudaGetSymbolAddress(&b0, g_b0);   cudaGetSymbolAddress(&b1, g_b1);
    cudaGetSymbolAddress(&b2, g_b2);
    cudaGetSymbolAddress(&a0h, g_a0h); cudaGetSymbolAddress(&a0l, g_a0l);
    cudaGetSymbolAddress(&a1h, g_a1h); cudaGetSymbolAddress(&a1l, g_a1l);
    cudaGetSymbolAddress(&a2h, g_a2h); cudaGetSymbolAddress(&a2l, g_a2l);

    cudaFuncSetAttribute(gemm_split_bf16,
                         cudaFuncAttributeMaxDynamicSharedMemorySize, GEMM_SMEM_TOTAL);

    // prep for gemm0 (+ prep for later layers)
    prep_weights_kernel<<<2048, 256>>>(wmu[0], wn[0], wlv[0], ml[0],
                                       (__nv_bfloat16*)wh0, (__nv_bfloat16*)wl0, HDIM * DIN);
    prep_bias_kernel<<<HDIM / 256, 256>>>(bmu[0], bn[0], blv[0], ml[0], (float*)b0, HDIM);
    split_x_kernel<<<2048, 256>>>(x, (__nv_bfloat16*)a0h, (__nv_bfloat16*)a0l, BDIM * DIN);
    prep_weights_kernel<<<2048, 256>>>(wmu[1], wn[1], wlv[1], ml[1],
                                       (__nv_bfloat16*)wh1, (__nv_bfloat16*)wl1, HDIM * HDIM);
    prep_bias_kernel<<<HDIM / 256, 256>>>(bmu[1], bn[1], blv[1], ml[1], (float*)b1, HDIM);

    // layer 0 GEMM
    gemm_split_bf16<<<dim3(HDIM / BN, BDIM / BM), NT, GEMM_SMEM_TOTAL>>>(
        (const __nv_bfloat16*)a0h, (const __nv_bfloat16*)a0l,
        (const __nv_bfloat16*)wh0, (const __nv_bfloat16*)wl0,
        (const float*)b0, DIN, HDIM, 1,
        (__nv_bfloat16*)a1h, (__nv_bfloat16*)a1l, nullptr);

    // prep for layer 2
    prep_weights_kernel<<<2048, 256>>>(wmu[2], wn[2], wlv[2], ml[2],
                                       (__nv_bfloat16*)wh2, (__nv_bfloat16*)wl2, DOUT * HDIM);
    prep_bias_kernel<<<DOUT / 256, 256>>>(bmu[2], bn[2], blv[2], ml[2], (float*)b2, DOUT);

    // layer 1
    gemm_split_bf16<<<dim3(HDIM / BN, BDIM / BM), NT, GEMM_SMEM_TOTAL>>>(
        (const __nv_bfloat16*)a1h, (const __nv_bfloat16*)a1l,
        (const __nv_bfloat16*)wh1, (const __nv_bfloat16*)wl1,
        (const float*)b1, HDIM, HDIM, 1,
        (__nv_bfloat16*)a2h, (__nv_bfloat16*)a2l, nullptr);

    // layer 2 -> fp32 logits into d_out
    gemm_split_bf16<<<dim3(DOUT / BN, BDIM / BM), NT, GEMM_SMEM_TOTAL>>>(
        (const __nv_bfloat16*)a2h, (const __nv_bfloat16*)a2l,
        (const __nv_bfloat16*)wh2, (const __nv_bfloat16*)wl2,
        (const float*)b2, HDIM, DOUT, 0,
        nullptr, nullptr, (float*)d_out);

    // softmax in place
    softmax_kernel<<<BDIM, 256>>>((float*)d_out);
}

// round 9
// speedup vs baseline: 1.0847x; 1.0847x over previous
#include <cuda_runtime.h>
#include <cuda_bf16.h>
#include <cstdint>
#include <cstddef>

// ---------------------------------------------------------------------------
// Problem dims
// ---------------------------------------------------------------------------
#define BDIM   8192
#define DIN    2048
#define HDIM   2048
#define DOUT   1024
#define NCOMP  4

// ---------------------------------------------------------------------------
// Helpers (sm_103-safe)
// ---------------------------------------------------------------------------
__device__ __forceinline__ uint32_t smem_u32(const void* p) {
    uint32_t a;
    asm("{ .reg .u64 t; cvta.to.shared.u64 t, %1; cvt.u32.u64 %0, t; }"
        : "=r"(a) : "l"(p));
    return a;
}

#define SMEM_SWIZZLE_128B(o) ((o) ^ (((o) >> 3) & 0x70))

__device__ __forceinline__ void cp_async16(uint32_t dst, const void* src) {
    asm volatile("cp.async.cg.shared.global [%0], [%1], 16;"
                 :: "r"(dst), "l"(__cvta_generic_to_global(src)));
}
#define CP_COMMIT() asm volatile("cp.async.commit_group;" ::: "memory")
#define CP_WAIT(n)  asm volatile("cp.async.wait_group %0;" :: "n"(n) : "memory")

__device__ __forceinline__ void ldsm4(uint32_t* r, uint32_t addr) {
    asm volatile("ldmatrix.sync.aligned.m8n8.x4.shared.b16 {%0,%1,%2,%3}, [%4];"
                 : "=r"(r[0]), "=r"(r[1]), "=r"(r[2]), "=r"(r[3]) : "r"(addr));
}

__device__ __forceinline__ void mma16816(float* d, const uint32_t* a,
                                         uint32_t b0, uint32_t b1) {
    asm volatile(
        "mma.sync.aligned.m16n8k16.row.col.f32.bf16.bf16.f32 "
        "{%0,%1,%2,%3}, {%4,%5,%6,%7}, {%8,%9}, {%0,%1,%2,%3};"
        : "+f"(d[0]), "+f"(d[1]), "+f"(d[2]), "+f"(d[3])
        : "r"(a[0]), "r"(a[1]), "r"(a[2]), "r"(a[3]), "r"(b0), "r"(b1));
}

// ---------------------------------------------------------------------------
// Scratch buffers (__device__ globals; no cudaMalloc allowed)
// ---------------------------------------------------------------------------
__device__ __align__(16) __nv_bfloat16 g_wh0[HDIM * DIN];
__device__ __align__(16) __nv_bfloat16 g_wl0[HDIM * DIN];
__device__ __align__(16) __nv_bfloat16 g_wh1[HDIM * HDIM];
__device__ __align__(16) __nv_bfloat16 g_wl1[HDIM * HDIM];
__device__ __align__(16) __nv_bfloat16 g_wh2[DOUT * HDIM];
__device__ __align__(16) __nv_bfloat16 g_wl2[DOUT * HDIM];
__device__ __align__(16) float g_b0[HDIM];
__device__ __align__(16) float g_b1[HDIM];
__device__ __align__(16) float g_b2[DOUT];
__device__ __align__(16) __nv_bfloat16 g_a0h[BDIM * DIN];
__device__ __align__(16) __nv_bfloat16 g_a0l[BDIM * DIN];
__device__ __align__(16) __nv_bfloat16 g_a1h[BDIM * HDIM];
__device__ __align__(16) __nv_bfloat16 g_a1l[BDIM * HDIM];
__device__ __align__(16) __nv_bfloat16 g_a2h[BDIM * HDIM];
__device__ __align__(16) __nv_bfloat16 g_a2l[BDIM * HDIM];

// ---------------------------------------------------------------------------
// Prep kernels: fold mixture into effective bf16 hi/lo weights + fp32 bias
// ---------------------------------------------------------------------------
__device__ __forceinline__ void mix_coefs(const float* ml, const float* lv,
                                          float* cmu, float* cn) {
    float m[NCOMP], mx = -1e30f, s = 0.f, e[NCOMP];
    #pragma unroll
    for (int k = 0; k < NCOMP; k++) { m[k] = ml[k]; mx = fmaxf(mx, m[k]); }
    #pragma unroll
    for (int k = 0; k < NCOMP; k++) { e[k] = expf(m[k] - mx); s += e[k]; }
    #pragma unroll
    for (int k = 0; k < NCOMP; k++) {
        float w = e[k] / s;
        cmu[k] = w;
        cn[k]  = w * expf(0.5f * lv[k]);
    }
}

__global__ void prep_weights_kernel(const float* __restrict__ wmu,
                                    const float* __restrict__ wn,
                                    const float* __restrict__ wlv,
                                    const float* __restrict__ ml,
                                    __nv_bfloat16* __restrict__ whi,
                                    __nv_bfloat16* __restrict__ wlo,
                                    int n) {
    __shared__ float cmu[NCOMP], cn[NCOMP];
    if (threadIdx.x == 0) mix_coefs(ml, wlv, cmu, cn);
    __syncthreads();
    int n4 = n >> 2;
    for (int i = blockIdx.x * blockDim.x + threadIdx.x; i < n4;
         i += gridDim.x * blockDim.x) {
        float4 acc = make_float4(0.f, 0.f, 0.f, 0.f);
        #pragma unroll
        for (int k = 0; k < NCOMP; k++) {
            float4 a = ((const float4*)wmu)[(size_t)k * n4 + i];
            float4 b = ((const float4*)wn)[(size_t)k * n4 + i];
            acc.x += cmu[k] * a.x + cn[k] * b.x;
            acc.y += cmu[k] * a.y + cn[k] * b.y;
            acc.z += cmu[k] * a.z + cn[k] * b.z;
            acc.w += cmu[k] * a.w + cn[k] * b.w;
        }
        __nv_bfloat16 h0 = __float2bfloat16(acc.x);
        __nv_bfloat16 h1 = __float2bfloat16(acc.y);
        __nv_bfloat16 h2 = __float2bfloat16(acc.z);
        __nv_bfloat16 h3 = __float2bfloat16(acc.w);
        __nv_bfloat16 l0 = __float2bfloat16(acc.x - __bfloat162float(h0));
        __nv_bfloat16 l1 = __float2bfloat16(acc.y - __bfloat162float(h1));
        __nv_bfloat16 l2 = __float2bfloat16(acc.z - __bfloat162float(h2));
        __nv_bfloat16 l3 = __float2bfloat16(acc.w - __bfloat162float(h3));
        ((__nv_bfloat162*)whi)[2 * (size_t)i]     = __halves2bfloat162(h0, h1);
        ((__nv_bfloat162*)whi)[2 * (size_t)i + 1] = __halves2bfloat162(h2, h3);
        ((__nv_bfloat162*)wlo)[2 * (size_t)i]     = __halves2bfloat162(l0, l1);
        ((__nv_bfloat162*)wlo)[2 * (size_t)i + 1] = __halves2bfloat162(l2, l3);
    }
}

__global__ void prep_bias_kernel(const float* __restrict__ bmu,
                                 const float* __restrict__ bn,
                                 const float* __restrict__ blv,
                                 const float* __restrict__ ml,
                                 float* __restrict__ out, int O) {
    __shared__ float cmu[NCOMP], cn[NCOMP];
    if (threadIdx.x == 0) mix_coefs(ml, blv, cmu, cn);
    __syncthreads();
    int o = blockIdx.x * blockDim.x + threadIdx.x;
    if (o < O) {
        float e = 0.f;
        #pragma unroll
        for (int k = 0; k < NCOMP; k++)
            e += cmu[k] * bmu[k * O + o] + cn[k] * bn[k * O + o];
        out[o] = e;
    }
}

__global__ void split_x_kernel(const float* __restrict__ x,
                               __nv_bfloat16* __restrict__ xh,
                               __nv_bfloat16* __restrict__ xl, int n) {
    int n4 = n >> 2;
    for (int i = blockIdx.x * blockDim.x + threadIdx.x; i < n4;
         i += gridDim.x * blockDim.x) {
        float4 v = ((const float4*)x)[i];
        __nv_bfloat16 h0 = __float2bfloat16(v.x);
        __nv_bfloat16 h1 = __float2bfloat16(v.y);
        __nv_bfloat16 h2 = __float2bfloat16(v.z);
        __nv_bfloat16 h3 = __float2bfloat16(v.w);
        __nv_bfloat16 l0 = __float2bfloat16(v.x - __bfloat162float(h0));
        __nv_bfloat16 l1 = __float2bfloat16(v.y - __bfloat162float(h1));
        __nv_bfloat16 l2 = __float2bfloat16(v.z - __bfloat162float(h2));
        __nv_bfloat16 l3 = __float2bfloat16(v.w - __bfloat162float(h3));
        ((__nv_bfloat162*)xh)[2 * (size_t)i]     = __halves2bfloat162(h0, h1);
        ((__nv_bfloat162*)xh)[2 * (size_t)i + 1] = __halves2bfloat162(h2, h3);
        ((__nv_bfloat162*)xl)[2 * (size_t)i]     = __halves2bfloat162(l0, l1);
        ((__nv_bfloat162*)xl)[2 * (size_t)i + 1] = __halves2bfloat162(l2, l3);
    }
}

// ---------------------------------------------------------------------------
// mma.sync GEMM:  C[B,O] = A[B,I] @ W[O,I]^T + bias   (split bf16 hi/lo)
// CTA tile 128x128, BK=64, 8 warps (2x4), warp tile 64x32.
// Small CTA tile -> L0/L1 grids = 1024 CTAs = 6.92 waves on 148 SMs
// (98.8% placement utilization vs 86.5% at 128x256).
// 2 cp.async stages (64 KB each), ONE __syncthreads per iter.
// ---------------------------------------------------------------------------
#define BM 128
#define BN 128
#define BK 64
#define NT 256
#define STAGE_BYTES 65536
#define OFF_AL 16384
#define OFF_WH 32768
#define OFF_WL 49152
#define GEMM_SMEM_TOTAL (2 * STAGE_BYTES)

__global__ void __launch_bounds__(NT, 1)
gemm_split_bf16(const __nv_bfloat16* __restrict__ Ah,
                const __nv_bfloat16* __restrict__ Al,
                const __nv_bfloat16* __restrict__ Wh,
                const __nv_bfloat16* __restrict__ Wl,
                const float* __restrict__ bias,
                int Idim, int Odim, int relu_split,
                __nv_bfloat16* __restrict__ Oh,
                __nv_bfloat16* __restrict__ Ol,
                float* __restrict__ Of) {
    extern __shared__ char smem[];
    const uint32_t sb = smem_u32(smem);
    const int tid = threadIdx.x;
    const int wid = tid >> 5, l = tid & 31;
    const int n0 = blockIdx.x * BN, m0 = blockIdx.y * BM;
    const int wm = (wid >> 2) * 64;    // warp m offset (2 m-bands)
    const int wn = (wid & 3) * 32;     // warp n offset (4 n-bands)
    const int lm = l >> 3, lr = l & 7; // ldmatrix lane decomposition

    float acc[4][4][4];
    #pragma unroll
    for (int i = 0; i < 4; i++)
        #pragma unroll
        for (int j = 0; j < 4; j++)
            #pragma unroll
            for (int q = 0; q < 4; q++) acc[i][j][q] = 0.f;

    const int nk = Idim / BK;

    // One stage: A 128x64 bf16 hi+lo (16 KB each), W 128x64 hi+lo.
    auto issue = [&](int s, int k0) {
        uint32_t base = sb + s * STAGE_BYTES;
        #pragma unroll
        for (int j = 0; j < 4; j++) {          // 1024 chunks per array
            int c = tid + j * NT;
            int row = c >> 3, col = c & 7;
            uint32_t so = SMEM_SWIZZLE_128B((uint32_t)(row * 128 + col * 16));
            size_t gA = (size_t)(m0 + row) * Idim + k0 + col * 8;
            size_t gW = (size_t)(n0 + row) * Idim + k0 + col * 8;
            cp_async16(base + so, Ah + gA);
            cp_async16(base + OFF_AL + so, Al + gA);
            cp_async16(base + OFF_WH + so, Wh + gW);
            cp_async16(base + OFF_WL + so, Wl + gW);
        }
    };

    issue(0, 0);
    CP_COMMIT();

    for (int it = 0; it < nk; ++it) {
        CP_WAIT(0);          // only group `it` pending -> stage ready
        __syncthreads();     // + WAR protection on stage (it+1)&1
        if (it + 1 < nk) {
            issue((it + 1) & 1, (it + 1) * BK);
            CP_COMMIT();
        }

        uint32_t bA = sb + (it & 1) * STAGE_BYTES;
        #pragma unroll
        for (int kk = 0; kk < 4; kk++) {
            uint32_t ah[4][4], al[4][4];
            #pragma unroll
            for (int mf = 0; mf < 4; mf++) {
                uint32_t off = SMEM_SWIZZLE_128B(
                    (uint32_t)((wm + mf * 16 + (lm & 1) * 8 + lr) * 128 +
                               (kk * 2 + (lm >> 1)) * 16));
                ldsm4(ah[mf], bA + off);
                ldsm4(al[mf], bA + OFF_AL + off);
            }
            #pragma unroll
            for (int nf2 = 0; nf2 < 2; nf2++) {
                uint32_t off = SMEM_SWIZZLE_128B(
                    (uint32_t)((wn + nf2 * 16 + (lm >> 1) * 8 + lr) * 128 +
                               (kk * 2 + (lm & 1)) * 16));
                uint32_t bh[4], bl[4];
                ldsm4(bh, bA + OFF_WH + off);
                ldsm4(bl, bA + OFF_WL + off);
                #pragma unroll
                for (int mf = 0; mf < 4; mf++) {
                    mma16816(acc[mf][2 * nf2],     ah[mf], bh[0], bh[1]);
                    mma16816(acc[mf][2 * nf2 + 1], ah[mf], bh[2], bh[3]);
                }
                #pragma unroll
                for (int mf = 0; mf < 4; mf++) {
                    mma16816(acc[mf][2 * nf2],     ah[mf], bl[0], bl[1]);
                    mma16816(acc[mf][2 * nf2 + 1], ah[mf], bl[2], bl[3]);
                }
                #pragma unroll
                for (int mf = 0; mf < 4; mf++) {
                    mma16816(acc[mf][2 * nf2],     al[mf], bh[0], bh[1]);
                    mma16816(acc[mf][2 * nf2 + 1], al[mf], bh[2], bh[3]);
                }
            }
        }
    }

    // Epilogue: bias (+relu+split) directly from register fragments.
    const int cb = n0 + wn;
    if (relu_split) {
        #pragma unroll
        for (int mf = 0; mf < 4; mf++) {
            int r0 = m0 + wm + mf * 16 + (l >> 2);
            #pragma unroll
            for (int nf = 0; nf < 4; nf++) {
                int col = cb + nf * 8 + 2 * (l & 3);
                float2 bv = *(const float2*)(bias + col);
                float v0 = fmaxf(acc[mf][nf][0] + bv.x, 0.f);
                float v1 = fmaxf(acc[mf][nf][1] + bv.y, 0.f);
                float v2 = fmaxf(acc[mf][nf][2] + bv.x, 0.f);
                float v3 = fmaxf(acc[mf][nf][3] + bv.y, 0.f);
                __nv_bfloat16 h0 = __float2bfloat16(v0);
                __nv_bfloat16 h1 = __float2bfloat16(v1);
                __nv_bfloat16 h2 = __float2bfloat16(v2);
                __nv_bfloat16 h3 = __float2bfloat16(v3);
                __nv_bfloat16 q0 = __float2bfloat16(v0 - __bfloat162float(h0));
                __nv_bfloat16 q1 = __float2bfloat16(v1 - __bfloat162float(h1));
                __nv_bfloat16 q2 = __float2bfloat16(v2 - __bfloat162float(h2));
                __nv_bfloat16 q3 = __float2bfloat16(v3 - __bfloat162float(h3));
                *(__nv_bfloat162*)(Oh + (size_t)r0 * Odim + col) = __halves2bfloat162(h0, h1);
                *(__nv_bfloat162*)(Oh + (size_t)(r0 + 8) * Odim + col) = __halves2bfloat162(h2, h3);
                *(__nv_bfloat162*)(Ol + (size_t)r0 * Odim + col) = __halves2bfloat162(q0, q1);
                *(__nv_bfloat162*)(Ol + (size_t)(r0 + 8) * Odim + col) = __halves2bfloat162(q2, q3);
            }
        }
    } else {
        #pragma unroll
        for (int mf = 0; mf < 4; mf++) {
            int r0 = m0 + wm + mf * 16 + (l >> 2);
            #pragma unroll
            for (int nf = 0; nf < 4; nf++) {
                int col = cb + nf * 8 + 2 * (l & 3);
                float2 bv = *(const float2*)(bias + col);
                float2 o0 = make_float2(acc[mf][nf][0] + bv.x, acc[mf][nf][1] + bv.y);
                float2 o1 = make_float2(acc[mf][nf][2] + bv.x, acc[mf][nf][3] + bv.y);
                *(float2*)(Of + (size_t)r0 * Odim + col) = o0;
                *(float2*)(Of + (size_t)(r0 + 8) * Odim + col) = o1;
            }
        }
    }
}

// ---------------------------------------------------------------------------
// Row softmax (in-place), 1024 cols, 256 threads/row
// ---------------------------------------------------------------------------
__global__ void softmax_kernel(float* __restrict__ io) {
    __shared__ float red[8];
    int b = blockIdx.x;
    float* row = io + (size_t)b * DOUT;
    int t = threadIdx.x;
    float v[4];
    float m = -1e30f;
    #pragma unroll
    for (int i = 0; i < 4; i++) { v[i] = row[t + 256 * i]; m = fmaxf(m, v[i]); }
    #pragma unroll
    for (int o = 16; o; o >>= 1) m = fmaxf(m, __shfl_xor_sync(0xffffffffu, m, o));
    if ((t & 31) == 0) red[t >> 5] = m;
    __syncthreads();
    m = red[0];
    #pragma unroll
    for (int w = 1; w < 8; w++) m = fmaxf(m, red[w]);
    float s = 0.f;
    #pragma unroll
    for (int i = 0; i < 4; i++) { v[i] = expf(v[i] - m); s += v[i]; }
    #pragma unroll
    for (int o = 16; o; o >>= 1) s += __shfl_xor_sync(0xffffffffu, s, o);
    __syncthreads();
    if ((t & 31) == 0) red[t >> 5] = s;
    __syncthreads();
    s = red[0];
    #pragma unroll
    for (int w = 1; w < 8; w++) s += red[w];
    float inv = 1.0f / s;
    #pragma unroll
    for (int i = 0; i < 4; i++) row[t + 256 * i] = v[i] * inv;
}

// ---------------------------------------------------------------------------
// Launcher
// ---------------------------------------------------------------------------
extern "C" void kernel_launch(void* const* d_in, const int* in_sizes, int n_in,
                              void* d_out, int out_size) {
    (void)in_sizes; (void)n_in; (void)out_size;
    const float* x   = (const float*)d_in[0];
    const float* wmu[3] = {(const float*)d_in[1],  (const float*)d_in[8],  (const float*)d_in[15]};
    const float* bmu[3] = {(const float*)d_in[2],  (const float*)d_in[9],  (const float*)d_in[16]};
    const float* wlv[3] = {(const float*)d_in[3],  (const float*)d_in[10], (const float*)d_in[17]};
    const float* blv[3] = {(const float*)d_in[4],  (const float*)d_in[11], (const float*)d_in[18]};
    const float* ml[3]  = {(const float*)d_in[5],  (const float*)d_in[12], (const float*)d_in[19]};
    const float* wn[3]  = {(const float*)d_in[6],  (const float*)d_in[13], (const float*)d_in[20]};
    const float* bn[3]  = {(const float*)d_in[7],  (const float*)d_in[14], (const float*)d_in[21]};

    void *wh0, *wl0, *wh1, *wl1, *wh2, *wl2, *b0, *b1, *b2;
    void *a0h, *a0l, *a1h, *a1l, *a2h, *a2l;
    cudaGetSymbolAddress(&wh0, g_wh0); cudaGetSymbolAddress(&wl0, g_wl0);
    cudaGetSymbolAddress(&wh1, g_wh1); cudaGetSymbolAddress(&wl1, g_wl1);
    cudaGetSymbolAddress(&wh2, g_wh2); cudaGetSymbolAddress(&wl2, g_wl2);
    cudaGetSymbolAddress(&b0, g_b0);   cudaGetSymbolAddress(&b1, g_b1);
    cudaGetSymbolAddress(&b2, g_b2);
    cudaGetSymbolAddress(&a0h, g_a0h); cudaGetSymbolAddress(&a0l, g_a0l);
    cudaGetSymbolAddress(&a1h, g_a1h); cudaGetSymbolAddress(&a1l, g_a1l);
    cudaGetSymbolAddress(&a2h, g_a2h); cudaGetSymbolAddress(&a2l, g_a2l);

    cudaFuncSetAttribute(gemm_split_bf16,
                         cudaFuncAttributeMaxDynamicSharedMemorySize, GEMM_SMEM_TOTAL);

    // prep for gemm0 (+ prep for later layers)
    prep_weights_kernel<<<2048, 256>>>(wmu[0], wn[0], wlv[0], ml[0],
                                       (__nv_bfloat16*)wh0, (__nv_bfloat16*)wl0, HDIM * DIN);
    prep_bias_kernel<<<HDIM / 256, 256>>>(bmu[0], bn[0], blv[0], ml[0], (float*)b0, HDIM);
    split_x_kernel<<<2048, 256>>>(x, (__nv_bfloat16*)a0h, (__nv_bfloat16*)a0l, BDIM * DIN);
    prep_weights_kernel<<<2048, 256>>>(wmu[1], wn[1], wlv[1], ml[1],
                                       (__nv_bfloat16*)wh1, (__nv_bfloat16*)wl1, HDIM * HDIM);
    prep_bias_kernel<<<HDIM / 256, 256>>>(bmu[1], bn[1], blv[1], ml[1], (float*)b1, HDIM);

    // layer 0 GEMM: grid (16, 64) = 1024 CTAs
    gemm_split_bf16<<<dim3(HDIM / BN, BDIM / BM), NT, GEMM_SMEM_TOTAL>>>(
        (const __nv_bfloat16*)a0h, (const __nv_bfloat16*)a0l,
        (const __nv_bfloat16*)wh0, (const __nv_bfloat16*)wl0,
        (const float*)b0, DIN, HDIM, 1,
        (__nv_bfloat16*)a1h, (__nv_bfloat16*)a1l, nullptr);

    // prep for layer 2
    prep_weights_kernel<<<2048, 256>>>(wmu[2], wn[2], wlv[2], ml[2],
                                       (__nv_bfloat16*)wh2, (__nv_bfloat16*)wl2, DOUT * HDIM);
    prep_bias_kernel<<<DOUT / 256, 256>>>(bmu[2], bn[2], blv[2], ml[2], (float*)b2, DOUT);

    // layer 1: grid (16, 64)
    gemm_split_bf16<<<dim3(HDIM / BN, BDIM / BM), NT, GEMM_SMEM_TOTAL>>>(
        (const __nv_bfloat16*)a1h, (const __nv_bfloat16*)a1l,
        (const __nv_bfloat16*)wh1, (const __nv_bfloat16*)wl1,
        (const float*)b1, HDIM, HDIM, 1,
        (__nv_bfloat16*)a2h, (__nv_bfloat16*)a2l, nullptr);

    // layer 2 -> fp32 logits into d_out: grid (8, 64)
    gemm_split_bf16<<<dim3(DOUT / BN, BDIM / BM), NT, GEMM_SMEM_TOTAL>>>(
        (const __nv_bfloat16*)a2h, (const __nv_bfloat16*)a2l,
        (const __nv_bfloat16*)wh2, (const __nv_bfloat16*)wl2,
        (const float*)b2, HDIM, DOUT, 0,
        nullptr, nullptr, (float*)d_out);

    // softmax in place
    softmax_kernel<<<BDIM, 256>>>((float*)d_out);
}